// round 13
// baseline (speedup 1.0000x reference)
#include <cuda_runtime.h>
#include <cuda_bf16.h>

#define MROWS 20000
#define DCH   128
#define FFH   512
#define BM    64
#define BK    32
#define ASTR  40      // halves per A row (32 data + 8 pad)
#define BSTR  136     // halves per B row (128 data + 8 pad)
#define NBLK  313     // ceil(20000/64)

// byte layout of one pipeline stage in dynamic smem
#define A_PLANE   5120                // 64*ASTR*2
#define B_PLANE   8704                // 32*BSTR*2
#define OFF_AL    (A_PLANE)           // 5120
#define OFF_BH    (2*A_PLANE)         // 10240
#define OFF_BL    (2*A_PLANE+B_PLANE) // 18944
#define STAGE_B   (2*A_PLANE+2*B_PLANE) // 27648
#define NSTAGE    3
#define SMEM_TOT  (NSTAGE*STAGE_B)    // 82944

// ---------------- scratch ----------------
__device__ __nv_bfloat16 g_wv_hi[3*DCH*DCH], g_wv_lo[3*DCH*DCH];
__device__ __nv_bfloat16 g_wo_hi[3*DCH*DCH], g_wo_lo[3*DCH*DCH];
__device__ __nv_bfloat16 g_w1_hi[3*DCH*FFH], g_w1_lo[3*DCH*FFH];
__device__ __nv_bfloat16 g_w2_hi[3*FFH*DCH], g_w2_lo[3*FFH*DCH];
__device__ __nv_bfloat16 g_h_hi[MROWS*DCH],  g_h_lo[MROWS*DCH];   // layer input (BN'd), split
__device__ __nv_bfloat16 g_P_hi[MROWS*DCH],  g_P_lo[MROWS*DCH];   // permuted V
__device__ __nv_bfloat16 g_z_hi[MROWS*DCH],  g_z_lo[MROWS*DCH];   // BN1(y0), split
__device__ __nv_bfloat16 g_f_hi[MROWS*FFH],  g_f_lo[MROWS*FFH];   // relu(ff1), split
__device__ float g_y0[MROWS*DCH];     // pre-BN1 fp32
__device__ float g_y1[MROWS*DCH];     // pre-BN2 fp32
__device__ float g_part [NBLK*DCH], g_part2[NBLK*DCH];
__device__ float g_scale1[DCH], g_shift1[DCH], g_scale2[DCH], g_shift2[DCH];
__device__ unsigned char g_mask[MROWS];

// ---------------- helpers ----------------
__device__ __forceinline__ unsigned sptr(const void* p){
    return (unsigned)__cvta_generic_to_shared(p);
}
__device__ __forceinline__ void split2(float a, float b, unsigned& hi, unsigned& lo){
    __nv_bfloat16 ha = __float2bfloat16(a), hb = __float2bfloat16(b);
    float ra = a - __bfloat162float(ha);
    float rb = b - __bfloat162float(hb);
    __nv_bfloat162 H; H.x = ha; H.y = hb;
    __nv_bfloat162 L = __floats2bfloat162_rn(ra, rb);
    hi = *reinterpret_cast<unsigned*>(&H);
    lo = *reinterpret_cast<unsigned*>(&L);
}
__device__ __forceinline__ void ldsm4(unsigned r[4], unsigned a){
    asm volatile("ldmatrix.sync.aligned.m8n8.x4.shared.b16 {%0,%1,%2,%3}, [%4];"
        : "=r"(r[0]), "=r"(r[1]), "=r"(r[2]), "=r"(r[3]) : "r"(a));
}
__device__ __forceinline__ void ldsm4t(unsigned r[4], unsigned a){
    asm volatile("ldmatrix.sync.aligned.m8n8.x4.trans.shared.b16 {%0,%1,%2,%3}, [%4];"
        : "=r"(r[0]), "=r"(r[1]), "=r"(r[2]), "=r"(r[3]) : "r"(a));
}
__device__ __forceinline__ void mma_b(float c[4], const unsigned a[4], unsigned b0, unsigned b1){
    asm volatile("mma.sync.aligned.m16n8k16.row.col.f32.bf16.bf16.f32 "
        "{%0,%1,%2,%3}, {%4,%5,%6,%7}, {%8,%9}, {%0,%1,%2,%3};"
        : "+f"(c[0]), "+f"(c[1]), "+f"(c[2]), "+f"(c[3])
        : "r"(a[0]), "r"(a[1]), "r"(a[2]), "r"(a[3]), "r"(b0), "r"(b1));
}
__device__ __forceinline__ void cpa(unsigned d, const void* s, int srcsize){
    asm volatile("cp.async.cg.shared.global [%0], [%1], 16, %2;"
        :: "r"(d), "l"(s), "r"(srcsize));
}

// ---------------- compute: one 64x128x32 stage, 3-pass split ----------------
__device__ __forceinline__ void compute_stage(unsigned base, float acc[8][4]){
    int lane = threadIdx.x & 31;
    int warp = threadIdx.x >> 5;
    int wm = warp >> 1, wn = warp & 1;     // 4 x 2 warps, warp tile 16x64
    unsigned saH = base, saL = base + OFF_AL, sbH = base + OFF_BH, sbL = base + OFF_BL;
    #pragma unroll
    for (int ks = 0; ks < 2; ks++){
        unsigned aH[4], aL[4];
        unsigned aoff = (unsigned)((wm*16 + (lane & 15))*(ASTR*2)
                                   + ks*32 + ((lane >> 4) << 4));
        ldsm4(aH, saH + aoff);
        ldsm4(aL, saL + aoff);
        #pragma unroll
        for (int p = 0; p < 4; p++){
            int kk = ks*16 + (lane & 15);
            int n  = wn*64 + p*16 + ((lane & 16) ? 8 : 0);
            unsigned boff = (unsigned)(kk*(BSTR*2) + n*2);
            unsigned t[4], u[4];
            ldsm4t(t, sbH + boff);
            ldsm4t(u, sbL + boff);
            mma_b(acc[2*p],   aH, t[0], t[1]);
            mma_b(acc[2*p+1], aH, t[2], t[3]);
            mma_b(acc[2*p],   aL, t[0], t[1]);
            mma_b(acc[2*p+1], aL, t[2], t[3]);
            mma_b(acc[2*p],   aH, u[0], u[1]);
            mma_b(acc[2*p+1], aH, u[2], u[3]);
        }
    }
}

// ---------------- pipelined mainloop (3-stage cp.async ring) ----------------
template<int S>
__device__ __forceinline__ void gemm_main(
    char* smem,
    const __nv_bfloat16* __restrict__ Ah, const __nv_bfloat16* __restrict__ Al,
    int lda, int row0,
    const __nv_bfloat16* __restrict__ Bh, const __nv_bfloat16* __restrict__ Bl,
    int ldb, int col0,
    float acc[8][4])
{
    unsigned base0 = sptr(smem);
    int tid = threadIdx.x;

    auto load = [&](int s){
        unsigned b = base0 + (unsigned)((s % NSTAGE) * STAGE_B);
        int k0 = s*BK;
        {   // A: 64 rows x 32 halves, 256 uint4 per plane -> 1 per thread
            int r = tid >> 2, c8 = (tid & 3) << 3;
            int gr = row0 + r;
            int sz = (gr < MROWS) ? 16 : 0;
            int grc = (gr < MROWS) ? gr : (MROWS - 1);
            size_t go = (size_t)grc*lda + k0 + c8;
            unsigned so = b + (unsigned)(r*(ASTR*2) + c8*2);
            cpa(so,          Ah + go, sz);
            cpa(so + OFF_AL, Al + go, sz);
        }
        #pragma unroll
        for (int i = 0; i < 2; i++){   // B: 32 rows x 128 halves, 512 uint4 per plane
            int j = tid + i*256;
            int r = j >> 4, c8 = (j & 15) << 3;
            size_t go = (size_t)(k0 + r)*ldb + col0 + c8;
            unsigned so = b + OFF_BH + (unsigned)(r*(BSTR*2) + c8*2);
            cpa(so,                     Bh + go, 16);
            cpa(so + (OFF_BL - OFF_BH), Bl + go, 16);
        }
        asm volatile("cp.async.commit_group;" ::: "memory");
    };

    load(0);
    load(1);
    for (int s = 0; s < S; s++){
        if (s + 2 < S){
            load(s + 2);
            asm volatile("cp.async.wait_group 2;" ::: "memory");
        } else if (s + 1 < S){
            asm volatile("cp.async.wait_group 1;" ::: "memory");
        } else {
            asm volatile("cp.async.wait_group 0;" ::: "memory");
        }
        __syncthreads();
        compute_stage(base0 + (unsigned)((s % NSTAGE) * STAGE_B), acc);
        __syncthreads();
    }
}

// deterministic per-block column sum/sumsq
__device__ __forceinline__ void block_stats(float acc[8][4], float* redS, float* redQ, int slot)
{
    int tid = threadIdx.x;
    int lane = tid & 31, warp = tid >> 5, wm = warp >> 1, wn = warp & 1;
    #pragma unroll
    for (int nt = 0; nt < 8; nt++){
        float a0=acc[nt][0], a1=acc[nt][1], a2=acc[nt][2], a3=acc[nt][3];
        float se = a0 + a2, so = a1 + a3;
        float qe = a0*a0 + a2*a2, qo = a1*a1 + a3*a3;
        #pragma unroll
        for (int off = 16; off >= 4; off >>= 1){
            se += __shfl_down_sync(0xffffffffu, se, off);
            so += __shfl_down_sync(0xffffffffu, so, off);
            qe += __shfl_down_sync(0xffffffffu, qe, off);
            qo += __shfl_down_sync(0xffffffffu, qo, off);
        }
        if (lane < 4){
            int c = wn*64 + nt*8 + lane*2;
            redS[wm*128 + c] = se; redS[wm*128 + c + 1] = so;
            redQ[wm*128 + c] = qe; redQ[wm*128 + c + 1] = qo;
        }
    }
    __syncthreads();
    if (tid < 128){
        float s = redS[tid] + redS[128+tid] + redS[256+tid] + redS[384+tid];
        float q = redQ[tid] + redQ[128+tid] + redQ[256+tid] + redQ[384+tid];
        g_part [slot*128 + tid] = s;
        g_part2[slot*128 + tid] = q;
    }
}

#define ACC_INIT float acc[8][4]; \
    _Pragma("unroll") for (int _j=0;_j<8;_j++) \
    _Pragma("unroll") for (int _k=0;_k<4;_k++) acc[_j][_k]=0.f;

#define EPI_COORDS int tid = threadIdx.x; int lane = tid & 31; int warp = tid >> 5; \
    int wm = warp >> 1, wn = warp & 1; \
    int rb = row0 + wm*16 + (lane>>2); \
    int cb = wn*64 + ((lane&3)<<1); (void)cb; (void)tid;

// ---------------- GEMM 1: P(permuted,split) = h @ Wv ----------------
__global__ __launch_bounds__(256, 2) void k_gemm_v(int l)
{
    extern __shared__ char smem[];
    ACC_INIT
    int row0 = blockIdx.x*BM;
    gemm_main<4>(smem, g_h_hi, g_h_lo, DCH, row0,
                 g_wv_hi + l*DCH*DCH, g_wv_lo + l*DCH*DCH, DCH, 0, acc);
    EPI_COORDS
    #pragma unroll
    for (int hf = 0; hf < 2; hf++){
        int r = rb + hf*8;
        if (r < MROWS){
            int m = r >> 3, rr = r & 7;
            #pragma unroll
            for (int nt = 0; nt < 8; nt++){
                int c = cb + nt*8;
                int g = c >> 4;
                size_t off = (size_t)(g*2500 + m)*DCH + (rr << 4) + (c & 15);
                unsigned hi, lo;
                split2(acc[nt][hf*2], acc[nt][hf*2+1], hi, lo);
                *(unsigned*)(g_P_hi + off) = hi;
                *(unsigned*)(g_P_lo + off) = lo;
            }
        }
    }
}

// ---------------- GEMM 2: y0 = h + mask*(P @ Wout), BN1 partial stats ----------------
__global__ __launch_bounds__(256, 2) void k_gemm_gat(int l)
{
    extern __shared__ char smem[];
    ACC_INIT
    int row0 = blockIdx.x*BM;
    gemm_main<4>(smem, g_P_hi, g_P_lo, DCH, row0,
                 g_wo_hi + l*DCH*DCH, g_wo_lo + l*DCH*DCH, DCH, 0, acc);
    EPI_COORDS
    #pragma unroll
    for (int hf = 0; hf < 2; hf++){
        int r = rb + hf*8;
        if (r < MROWS){
            float mk = g_mask[r] ? 1.f : 0.f;
            #pragma unroll
            for (int nt = 0; nt < 8; nt++){
                int c = cb + nt*8;
                size_t off = (size_t)r*DCH + c;
                unsigned ph = *(const unsigned*)(g_h_hi + off);
                unsigned pl = *(const unsigned*)(g_h_lo + off);
                __nv_bfloat162 Hh = *reinterpret_cast<__nv_bfloat162*>(&ph);
                __nv_bfloat162 Hl = *reinterpret_cast<__nv_bfloat162*>(&pl);
                float h0 = __bfloat162float(Hh.x) + __bfloat162float(Hl.x);
                float h1 = __bfloat162float(Hh.y) + __bfloat162float(Hl.y);
                float v0 = fmaf(mk, acc[nt][hf*2+0], h0);
                float v1 = fmaf(mk, acc[nt][hf*2+1], h1);
                *(float2*)(g_y0 + off) = make_float2(v0, v1);
                acc[nt][hf*2+0] = v0; acc[nt][hf*2+1] = v1;
            }
        } else {
            #pragma unroll
            for (int nt = 0; nt < 8; nt++){ acc[nt][hf*2+0]=0.f; acc[nt][hf*2+1]=0.f; }
        }
    }
    block_stats(acc, (float*)smem, (float*)(smem + 2048), blockIdx.x);
}

// ---------------- GEMM 3: f = relu(z @ W1 + b1), split output ----------------
__global__ __launch_bounds__(256, 2) void k_gemm_ff1(int l, const float* __restrict__ bias)
{
    extern __shared__ char smem[];
    ACC_INIT
    int row0 = blockIdx.x*BM;
    int col0 = blockIdx.y*128;
    gemm_main<4>(smem, g_z_hi, g_z_lo, DCH, row0,
                 g_w1_hi + l*DCH*FFH, g_w1_lo + l*DCH*FFH, FFH, col0, acc);
    EPI_COORDS
    #pragma unroll
    for (int hf = 0; hf < 2; hf++){
        int r = rb + hf*8;
        if (r < MROWS){
            #pragma unroll
            for (int nt = 0; nt < 8; nt++){
                int c = cb + nt*8;
                float v0 = fmaxf(acc[nt][hf*2+0] + bias[col0+c],   0.f);
                float v1 = fmaxf(acc[nt][hf*2+1] + bias[col0+c+1], 0.f);
                unsigned hi, lo;
                split2(v0, v1, hi, lo);
                size_t off = (size_t)r*FFH + col0 + c;
                *(unsigned*)(g_f_hi + off) = hi;
                *(unsigned*)(g_f_lo + off) = lo;
            }
        }
    }
}

// ---------------- GEMM 4: y1 = z + f @ W2 + b2, BN2 partial stats ----------------
__global__ __launch_bounds__(256, 2) void k_gemm_ff2(int l, const float* __restrict__ bias)
{
    extern __shared__ char smem[];
    ACC_INIT
    int row0 = blockIdx.x*BM;
    gemm_main<16>(smem, g_f_hi, g_f_lo, FFH, row0,
                  g_w2_hi + l*FFH*DCH, g_w2_lo + l*FFH*DCH, DCH, 0, acc);
    EPI_COORDS
    #pragma unroll
    for (int hf = 0; hf < 2; hf++){
        int r = rb + hf*8;
        if (r < MROWS){
            #pragma unroll
            for (int nt = 0; nt < 8; nt++){
                int c = cb + nt*8;
                size_t off = (size_t)r*DCH + c;
                unsigned ph = *(const unsigned*)(g_z_hi + off);
                unsigned pl = *(const unsigned*)(g_z_lo + off);
                __nv_bfloat162 Zh = *reinterpret_cast<__nv_bfloat162*>(&ph);
                __nv_bfloat162 Zl = *reinterpret_cast<__nv_bfloat162*>(&pl);
                float z0 = __bfloat162float(Zh.x) + __bfloat162float(Zl.x);
                float z1 = __bfloat162float(Zh.y) + __bfloat162float(Zl.y);
                float v0 = z0 + acc[nt][hf*2+0] + bias[c];
                float v1 = z1 + acc[nt][hf*2+1] + bias[c+1];
                *(float2*)(g_y1 + off) = make_float2(v0, v1);
                acc[nt][hf*2+0] = v0; acc[nt][hf*2+1] = v1;
            }
        } else {
            #pragma unroll
            for (int nt = 0; nt < 8; nt++){ acc[nt][hf*2+0]=0.f; acc[nt][hf*2+1]=0.f; }
        }
    }
    block_stats(acc, (float*)smem, (float*)(smem + 2048), blockIdx.x);
}

// ---------------- small kernels ----------------
__global__ void k_prep_all(const float* __restrict__ Wv, const float* __restrict__ Wo,
                           const float* __restrict__ W1, const float* __restrict__ W2){
    int idx = blockIdx.x*256 + threadIdx.x;
    if (idx < 49152){
        int l = idx / (DCH*DCH);
        int rmd = idx % (DCH*DCH);
        int d = rmd / DCH, col = rmd % DCH;
        int g = col >> 4, k = col & 15;
        float v = Wv[((l*8 + g)*DCH + d)*16 + k];
        __nv_bfloat16 h = __float2bfloat16(v);
        g_wv_hi[idx] = h;
        g_wv_lo[idx] = __float2bfloat16(v - __bfloat162float(h));
    } else if (idx < 98304){
        int i = idx - 49152;
        float v = Wo[i];
        __nv_bfloat16 h = __float2bfloat16(v);
        g_wo_hi[i] = h; g_wo_lo[i] = __float2bfloat16(v - __bfloat162float(h));
    } else if (idx < 294912){
        int i = idx - 98304;
        float v = W1[i];
        __nv_bfloat16 h = __float2bfloat16(v);
        g_w1_hi[i] = h; g_w1_lo[i] = __float2bfloat16(v - __bfloat162float(h));
    } else if (idx < 491520){
        int i = idx - 294912;
        float v = W2[i];
        __nv_bfloat16 h = __float2bfloat16(v);
        g_w2_hi[i] = h; g_w2_lo[i] = __float2bfloat16(v - __bfloat162float(h));
    } else if (idx < 511520){
        g_mask[idx - 491520] = 0;
    }
}

__global__ void k_scatter_mask(const int* __restrict__ ei, int E){
    int e = blockIdx.x*256 + threadIdx.x;
    if (e < E) g_mask[ei[E + e]] = 1;   // dst row
}

// x -> h split (layer 0 input)
__global__ void k_split_x(const float4* __restrict__ x){
    int i = blockIdx.x*256 + threadIdx.x;     // 640000 float4 exactly
    float4 v = x[i];
    unsigned h0,l0,h1,l1;
    split2(v.x, v.y, h0, l0);
    split2(v.z, v.w, h1, l1);
    *(uint2*)(g_h_hi + (size_t)i*4) = make_uint2(h0, h1);
    *(uint2*)(g_h_lo + (size_t)i*4) = make_uint2(l0, l1);
}

__global__ void k_finalize(int nslots, const float* __restrict__ w,
                           const float* __restrict__ b, int which){
    int c = threadIdx.x;   // 128
    float s = 0.f, q = 0.f;
    for (int i = 0; i < nslots; i++){ s += g_part[i*128 + c]; q += g_part2[i*128 + c]; }
    float inv = 1.f / (float)MROWS;
    float mu = s * inv;
    float var = q * inv - mu*mu;
    float sc = rsqrtf(var + 1e-5f) * w[c];
    if (which == 1){ g_scale1[c] = sc; g_shift1[c] = b[c] - mu*sc; }
    else           { g_scale2[c] = sc; g_shift2[c] = b[c] - mu*sc; }
}

// BN1 apply + split: y0 -> z
__global__ void k_bnsplit(){
    int i = blockIdx.x*256 + threadIdx.x;     // 640000 float4
    float4 v = ((const float4*)g_y0)[i];
    int c = (i & 31) << 2;
    v.x = fmaf(v.x, g_scale1[c+0], g_shift1[c+0]);
    v.y = fmaf(v.y, g_scale1[c+1], g_shift1[c+1]);
    v.z = fmaf(v.z, g_scale1[c+2], g_shift1[c+2]);
    v.w = fmaf(v.w, g_scale1[c+3], g_shift1[c+3]);
    unsigned h0,l0,h1,l1;
    split2(v.x, v.y, h0, l0);
    split2(v.z, v.w, h1, l1);
    *(uint2*)(g_z_hi + (size_t)i*4) = make_uint2(h0, h1);
    *(uint2*)(g_z_lo + (size_t)i*4) = make_uint2(l0, l1);
}

// BN2 apply: y1 -> h split (next layer) or fp32 out (last layer)
__global__ void k_bn2(int last, float4* __restrict__ out){
    int i = blockIdx.x*256 + threadIdx.x;
    float4 v = ((const float4*)g_y1)[i];
    int c = (i & 31) << 2;
    v.x = fmaf(v.x, g_scale2[c+0], g_shift2[c+0]);
    v.y = fmaf(v.y, g_scale2[c+1], g_shift2[c+1]);
    v.z = fmaf(v.z, g_scale2[c+2], g_shift2[c+2]);
    v.w = fmaf(v.w, g_scale2[c+3], g_shift2[c+3]);
    if (last){
        out[i] = v;
    } else {
        unsigned h0,l0,h1,l1;
        split2(v.x, v.y, h0, l0);
        split2(v.z, v.w, h1, l1);
        *(uint2*)(g_h_hi + (size_t)i*4) = make_uint2(h0, h1);
        *(uint2*)(g_h_lo + (size_t)i*4) = make_uint2(l0, l1);
    }
}

// ---------------- launch ----------------
extern "C" void kernel_launch(void* const* d_in, const int* in_sizes, int n_in,
                              void* d_out, int out_size) {
    const float* x    = (const float*)d_in[0];
    const int*   ei   = (const int*)  d_in[1];
    const float* Wv   = (const float*)d_in[4];
    const float* Wout = (const float*)d_in[5];
    const float* bn1w = (const float*)d_in[6];
    const float* bn1b = (const float*)d_in[7];
    const float* W1   = (const float*)d_in[8];
    const float* b1   = (const float*)d_in[9];
    const float* W2   = (const float*)d_in[10];
    const float* b2   = (const float*)d_in[11];
    const float* bn2w = (const float*)d_in[12];
    const float* bn2b = (const float*)d_in[13];
    float* out = (float*)d_out;
    int E = in_sizes[1] / 2;

    cudaFuncSetAttribute(k_gemm_v,   cudaFuncAttributeMaxDynamicSharedMemorySize, SMEM_TOT);
    cudaFuncSetAttribute(k_gemm_gat, cudaFuncAttributeMaxDynamicSharedMemorySize, SMEM_TOT);
    cudaFuncSetAttribute(k_gemm_ff1, cudaFuncAttributeMaxDynamicSharedMemorySize, SMEM_TOT);
    cudaFuncSetAttribute(k_gemm_ff2, cudaFuncAttributeMaxDynamicSharedMemorySize, SMEM_TOT);

    k_prep_all<<<1999, 256>>>(Wv, Wout, W1, W2);
    k_scatter_mask<<<(E + 255)/256, 256>>>(ei, E);
    k_split_x<<<2500, 256>>>((const float4*)x);

    for (int l = 0; l < 3; l++){
        k_gemm_v  <<<NBLK, 256, SMEM_TOT>>>(l);
        k_gemm_gat<<<NBLK, 256, SMEM_TOT>>>(l);
        k_finalize<<<1, 128>>>(NBLK, bn1w + l*128, bn1b + l*128, 1);
        k_bnsplit <<<2500, 256>>>();
        dim3 gf(NBLK, 4);
        k_gemm_ff1<<<gf, 256, SMEM_TOT>>>(l, b1 + l*512);
        k_gemm_ff2<<<NBLK, 256, SMEM_TOT>>>(l, b2 + l*128);
        k_finalize<<<1, 128>>>(NBLK, bn2w + l*128, bn2b + l*128, 2);
        k_bn2     <<<2500, 256>>>((l == 2) ? 1 : 0, (float4*)out);
    }
}

// round 15
// speedup vs baseline: 1.0249x; 1.0249x over previous
#include <cuda_runtime.h>
#include <cuda_bf16.h>

#define MROWS 20000
#define DCH   128
#define FFH   512
#define BM    64
#define BK    32
#define ASTR  40      // halves per A row (32 data + 8 pad)
#define BSTR  136     // halves per B row (128 data + 8 pad)
#define NBLK  313     // ceil(20000/64)

// byte layout of one pipeline stage in dynamic smem
#define A_PLANE   5120                // 64*ASTR*2
#define B_PLANE   8704                // 32*BSTR*2
#define OFF_AL    (A_PLANE)
#define OFF_BH    (2*A_PLANE)
#define OFF_BL    (2*A_PLANE+B_PLANE)
#define STAGE_B   (2*A_PLANE+2*B_PLANE) // 27648
#define NSTAGE    2
#define SMEM_TOT  (NSTAGE*STAGE_B)    // 55296  -> 4 CTAs/SM = 221KB

// ---------------- scratch ----------------
__device__ __nv_bfloat16 g_wv_hi[3*DCH*DCH], g_wv_lo[3*DCH*DCH];
__device__ __nv_bfloat16 g_wo_hi[3*DCH*DCH], g_wo_lo[3*DCH*DCH];
__device__ __nv_bfloat16 g_w1_hi[3*DCH*FFH], g_w1_lo[3*DCH*FFH];
__device__ __nv_bfloat16 g_w2_hi[3*FFH*DCH], g_w2_lo[3*FFH*DCH];
__device__ __nv_bfloat16 g_h_hi[MROWS*DCH],  g_h_lo[MROWS*DCH];
__device__ __nv_bfloat16 g_P_hi[MROWS*DCH],  g_P_lo[MROWS*DCH];
__device__ __nv_bfloat16 g_z_hi[MROWS*DCH],  g_z_lo[MROWS*DCH];
__device__ __nv_bfloat16 g_f_hi[MROWS*FFH],  g_f_lo[MROWS*FFH];
__device__ float g_y0[MROWS*DCH];
__device__ float g_y1[MROWS*DCH];
__device__ float g_part [NBLK*DCH], g_part2[NBLK*DCH];
__device__ float g_scale1[DCH], g_shift1[DCH], g_scale2[DCH], g_shift2[DCH];
__device__ unsigned char g_mask[MROWS];

// ---------------- helpers ----------------
__device__ __forceinline__ unsigned sptr(const void* p){
    return (unsigned)__cvta_generic_to_shared(p);
}
__device__ __forceinline__ void split2(float a, float b, unsigned& hi, unsigned& lo){
    __nv_bfloat16 ha = __float2bfloat16(a), hb = __float2bfloat16(b);
    float ra = a - __bfloat162float(ha);
    float rb = b - __bfloat162float(hb);
    __nv_bfloat162 H; H.x = ha; H.y = hb;
    __nv_bfloat162 L = __floats2bfloat162_rn(ra, rb);
    hi = *reinterpret_cast<unsigned*>(&H);
    lo = *reinterpret_cast<unsigned*>(&L);
}
__device__ __forceinline__ void ldsm4(unsigned r[4], unsigned a){
    asm volatile("ldmatrix.sync.aligned.m8n8.x4.shared.b16 {%0,%1,%2,%3}, [%4];"
        : "=r"(r[0]), "=r"(r[1]), "=r"(r[2]), "=r"(r[3]) : "r"(a));
}
__device__ __forceinline__ void ldsm4t(unsigned r[4], unsigned a){
    asm volatile("ldmatrix.sync.aligned.m8n8.x4.trans.shared.b16 {%0,%1,%2,%3}, [%4];"
        : "=r"(r[0]), "=r"(r[1]), "=r"(r[2]), "=r"(r[3]) : "r"(a));
}
__device__ __forceinline__ void mma_b(float c[4], const unsigned a[4], unsigned b0, unsigned b1){
    asm volatile("mma.sync.aligned.m16n8k16.row.col.f32.bf16.bf16.f32 "
        "{%0,%1,%2,%3}, {%4,%5,%6,%7}, {%8,%9}, {%0,%1,%2,%3};"
        : "+f"(c[0]), "+f"(c[1]), "+f"(c[2]), "+f"(c[3])
        : "r"(a[0]), "r"(a[1]), "r"(a[2]), "r"(a[3]), "r"(b0), "r"(b1));
}
__device__ __forceinline__ void cpa(unsigned d, const void* s, int srcsize){
    asm volatile("cp.async.cg.shared.global [%0], [%1], 16, %2;"
        :: "r"(d), "l"(s), "r"(srcsize));
}

// ---------------- compute: one 64x128x32 stage, 3-pass split ----------------
// 4 warps, warp grid 2m x 2n, warp tile 32x64
__device__ __forceinline__ void compute_stage(unsigned base, float acc[2][8][4]){
    int lane = threadIdx.x & 31;
    int warp = threadIdx.x >> 5;       // 0..3
    int wm = warp >> 1, wn = warp & 1;
    unsigned saH = base, saL = base + OFF_AL, sbH = base + OFF_BH, sbL = base + OFF_BL;
    #pragma unroll
    for (int ks = 0; ks < 2; ks++){
        unsigned aH[2][4], aL[2][4];
        #pragma unroll
        for (int mt = 0; mt < 2; mt++){
            unsigned aoff = (unsigned)((wm*32 + mt*16 + (lane & 15))*(ASTR*2)
                                       + ks*32 + ((lane >> 4) << 4));
            ldsm4(aH[mt], saH + aoff);
            ldsm4(aL[mt], saL + aoff);
        }
        #pragma unroll
        for (int p = 0; p < 4; p++){
            int kk = ks*16 + (lane & 15);
            int n  = wn*64 + p*16 + ((lane & 16) ? 8 : 0);
            unsigned boff = (unsigned)(kk*(BSTR*2) + n*2);
            unsigned t[4], u[4];
            ldsm4t(t, sbH + boff);
            ldsm4t(u, sbL + boff);
            #pragma unroll
            for (int mt = 0; mt < 2; mt++){
                mma_b(acc[mt][2*p],   aH[mt], t[0], t[1]);
                mma_b(acc[mt][2*p+1], aH[mt], t[2], t[3]);
                mma_b(acc[mt][2*p],   aL[mt], t[0], t[1]);
                mma_b(acc[mt][2*p+1], aL[mt], t[2], t[3]);
                mma_b(acc[mt][2*p],   aH[mt], u[0], u[1]);
                mma_b(acc[mt][2*p+1], aH[mt], u[2], u[3]);
            }
        }
    }
}

// ---------------- pipelined mainloop (2-stage cp.async, 128 threads) ----------------
template<int S>
__device__ __forceinline__ void gemm_main(
    char* smem,
    const __nv_bfloat16* __restrict__ Ah, const __nv_bfloat16* __restrict__ Al,
    int lda, int row0,
    const __nv_bfloat16* __restrict__ Bh, const __nv_bfloat16* __restrict__ Bl,
    int ldb, int col0,
    float acc[2][8][4])
{
    unsigned base0 = sptr(smem);
    int tid = threadIdx.x;

    auto load = [&](int s){
        unsigned b = base0 + (unsigned)((s & 1) * STAGE_B);
        int k0 = s*BK;
        #pragma unroll
        for (int i = 0; i < 2; i++){   // A: 64 rows x 4 uint4 = 256 per plane
            int j = tid + i*128;
            int r = j >> 2, c8 = (j & 3) << 3;
            int gr = row0 + r;
            int sz = (gr < MROWS) ? 16 : 0;
            int grc = (gr < MROWS) ? gr : (MROWS - 1);
            size_t go = (size_t)grc*lda + k0 + c8;
            unsigned so = b + (unsigned)(r*(ASTR*2) + c8*2);
            cpa(so,          Ah + go, sz);
            cpa(so + OFF_AL, Al + go, sz);
        }
        #pragma unroll
        for (int i = 0; i < 4; i++){   // B: 32 rows x 16 uint4 = 512 per plane
            int j = tid + i*128;
            int r = j >> 4, c8 = (j & 15) << 3;
            size_t go = (size_t)(k0 + r)*ldb + col0 + c8;
            unsigned so = b + OFF_BH + (unsigned)(r*(BSTR*2) + c8*2);
            cpa(so,                     Bh + go, 16);
            cpa(so + (OFF_BL - OFF_BH), Bl + go, 16);
        }
        asm volatile("cp.async.commit_group;" ::: "memory");
    };

    load(0);
    for (int s = 0; s < S; s++){
        if (s + 1 < S){
            load(s + 1);
            asm volatile("cp.async.wait_group 1;" ::: "memory");
        } else {
            asm volatile("cp.async.wait_group 0;" ::: "memory");
        }
        __syncthreads();
        compute_stage(base0 + (unsigned)((s & 1) * STAGE_B), acc);
        __syncthreads();
    }
}

// deterministic per-block column sum/sumsq (4 warps: wm in {0,1})
__device__ __forceinline__ void block_stats(float acc[2][8][4], float* redS, float* redQ, int slot)
{
    int tid = threadIdx.x;
    int lane = tid & 31, warp = tid >> 5, wm = warp >> 1, wn = warp & 1;
    #pragma unroll
    for (int nt = 0; nt < 8; nt++){
        float se=0.f, so=0.f, qe=0.f, qo=0.f;
        #pragma unroll
        for (int mt = 0; mt < 2; mt++){
            float a0=acc[mt][nt][0], a1=acc[mt][nt][1], a2=acc[mt][nt][2], a3=acc[mt][nt][3];
            se += a0 + a2; so += a1 + a3;
            qe += a0*a0 + a2*a2; qo += a1*a1 + a3*a3;
        }
        #pragma unroll
        for (int off = 16; off >= 4; off >>= 1){
            se += __shfl_down_sync(0xffffffffu, se, off);
            so += __shfl_down_sync(0xffffffffu, so, off);
            qe += __shfl_down_sync(0xffffffffu, qe, off);
            qo += __shfl_down_sync(0xffffffffu, qo, off);
        }
        if (lane < 4){
            int c = wn*64 + nt*8 + lane*2;
            redS[wm*128 + c] = se; redS[wm*128 + c + 1] = so;
            redQ[wm*128 + c] = qe; redQ[wm*128 + c + 1] = qo;
        }
    }
    __syncthreads();
    if (tid < 128){
        float s = redS[tid] + redS[128+tid];
        float q = redQ[tid] + redQ[128+tid];
        g_part [slot*128 + tid] = s;
        g_part2[slot*128 + tid] = q;
    }
}

#define ACC_INIT float acc[2][8][4]; \
    _Pragma("unroll") for (int _i=0;_i<2;_i++) \
    _Pragma("unroll") for (int _j=0;_j<8;_j++) \
    _Pragma("unroll") for (int _k=0;_k<4;_k++) acc[_i][_j][_k]=0.f;

#define EPI_COORDS int tid = threadIdx.x; int lane = tid & 31; int warp = tid >> 5; \
    int wm = warp >> 1, wn = warp & 1; \
    int rb = row0 + wm*32 + (lane>>2); \
    int cb = wn*64 + ((lane&3)<<1); (void)cb; (void)tid;

// ---------------- GEMM 1: P(permuted,split) = h @ Wv ----------------
__global__ __launch_bounds__(128, 4) void k_gemm_v(int l)
{
    extern __shared__ char smem[];
    ACC_INIT
    int row0 = blockIdx.x*BM;
    gemm_main<4>(smem, g_h_hi, g_h_lo, DCH, row0,
                 g_wv_hi + l*DCH*DCH, g_wv_lo + l*DCH*DCH, DCH, 0, acc);
    EPI_COORDS
    #pragma unroll
    for (int mt = 0; mt < 2; mt++)
    #pragma unroll
    for (int hf = 0; hf < 2; hf++){
        int r = rb + mt*16 + hf*8;
        if (r < MROWS){
            int m = r >> 3, rr = r & 7;
            #pragma unroll
            for (int nt = 0; nt < 8; nt++){
                int c = cb + nt*8;
                int g = c >> 4;
                size_t off = (size_t)(g*2500 + m)*DCH + (rr << 4) + (c & 15);
                unsigned hi, lo;
                split2(acc[mt][nt][hf*2], acc[mt][nt][hf*2+1], hi, lo);
                *(unsigned*)(g_P_hi + off) = hi;
                *(unsigned*)(g_P_lo + off) = lo;
            }
        }
    }
}

// ---------------- GEMM 2: y0 = h + mask*(P @ Wout), BN1 partial stats ----------------
__global__ __launch_bounds__(128, 4) void k_gemm_gat(int l)
{
    extern __shared__ char smem[];
    ACC_INIT
    int row0 = blockIdx.x*BM;
    gemm_main<4>(smem, g_P_hi, g_P_lo, DCH, row0,
                 g_wo_hi + l*DCH*DCH, g_wo_lo + l*DCH*DCH, DCH, 0, acc);
    EPI_COORDS
    #pragma unroll
    for (int mt = 0; mt < 2; mt++)
    #pragma unroll
    for (int hf = 0; hf < 2; hf++){
        int r = rb + mt*16 + hf*8;
        if (r < MROWS){
            float mk = g_mask[r] ? 1.f : 0.f;
            #pragma unroll
            for (int nt = 0; nt < 8; nt++){
                int c = cb + nt*8;
                size_t off = (size_t)r*DCH + c;
                unsigned ph = *(const unsigned*)(g_h_hi + off);
                unsigned pl = *(const unsigned*)(g_h_lo + off);
                __nv_bfloat162 Hh = *reinterpret_cast<__nv_bfloat162*>(&ph);
                __nv_bfloat162 Hl = *reinterpret_cast<__nv_bfloat162*>(&pl);
                float h0 = __bfloat162float(Hh.x) + __bfloat162float(Hl.x);
                float h1 = __bfloat162float(Hh.y) + __bfloat162float(Hl.y);
                float v0 = fmaf(mk, acc[mt][nt][hf*2+0], h0);
                float v1 = fmaf(mk, acc[mt][nt][hf*2+1], h1);
                *(float2*)(g_y0 + off) = make_float2(v0, v1);
                acc[mt][nt][hf*2+0] = v0; acc[mt][nt][hf*2+1] = v1;
            }
        } else {
            #pragma unroll
            for (int nt = 0; nt < 8; nt++){ acc[mt][nt][hf*2+0]=0.f; acc[mt][nt][hf*2+1]=0.f; }
        }
    }
    block_stats(acc, (float*)smem, (float*)(smem + 2048), blockIdx.x);
}

// ---------------- GEMM 3: f = relu(z @ W1 + b1), split output ----------------
__global__ __launch_bounds__(128, 4) void k_gemm_ff1(int l, const float* __restrict__ bias)
{
    extern __shared__ char smem[];
    ACC_INIT
    int row0 = blockIdx.x*BM;
    int col0 = blockIdx.y*128;
    gemm_main<4>(smem, g_z_hi, g_z_lo, DCH, row0,
                 g_w1_hi + l*DCH*FFH, g_w1_lo + l*DCH*FFH, FFH, col0, acc);
    EPI_COORDS
    #pragma unroll
    for (int mt = 0; mt < 2; mt++)
    #pragma unroll
    for (int hf = 0; hf < 2; hf++){
        int r = rb + mt*16 + hf*8;
        if (r < MROWS){
            #pragma unroll
            for (int nt = 0; nt < 8; nt++){
                int c = cb + nt*8;
                float v0 = fmaxf(acc[mt][nt][hf*2+0] + bias[col0+c],   0.f);
                float v1 = fmaxf(acc[mt][nt][hf*2+1] + bias[col0+c+1], 0.f);
                unsigned hi, lo;
                split2(v0, v1, hi, lo);
                size_t off = (size_t)r*FFH + col0 + c;
                *(unsigned*)(g_f_hi + off) = hi;
                *(unsigned*)(g_f_lo + off) = lo;
            }
        }
    }
}

// ---------------- GEMM 4: y1 = z + f @ W2 + b2, BN2 partial stats ----------------
__global__ __launch_bounds__(128, 4) void k_gemm_ff2(int l, const float* __restrict__ bias)
{
    extern __shared__ char smem[];
    ACC_INIT
    int row0 = blockIdx.x*BM;
    gemm_main<16>(smem, g_f_hi, g_f_lo, FFH, row0,
                  g_w2_hi + l*FFH*DCH, g_w2_lo + l*FFH*DCH, DCH, 0, acc);
    EPI_COORDS
    #pragma unroll
    for (int mt = 0; mt < 2; mt++)
    #pragma unroll
    for (int hf = 0; hf < 2; hf++){
        int r = rb + mt*16 + hf*8;
        if (r < MROWS){
            #pragma unroll
            for (int nt = 0; nt < 8; nt++){
                int c = cb + nt*8;
                size_t off = (size_t)r*DCH + c;
                unsigned ph = *(const unsigned*)(g_z_hi + off);
                unsigned pl = *(const unsigned*)(g_z_lo + off);
                __nv_bfloat162 Zh = *reinterpret_cast<__nv_bfloat162*>(&ph);
                __nv_bfloat162 Zl = *reinterpret_cast<__nv_bfloat162*>(&pl);
                float z0 = __bfloat162float(Zh.x) + __bfloat162float(Zl.x);
                float z1 = __bfloat162float(Zh.y) + __bfloat162float(Zl.y);
                float v0 = z0 + acc[mt][nt][hf*2+0] + bias[c];
                float v1 = z1 + acc[mt][nt][hf*2+1] + bias[c+1];
                *(float2*)(g_y1 + off) = make_float2(v0, v1);
                acc[mt][nt][hf*2+0] = v0; acc[mt][nt][hf*2+1] = v1;
            }
        } else {
            #pragma unroll
            for (int nt = 0; nt < 8; nt++){ acc[mt][nt][hf*2+0]=0.f; acc[mt][nt][hf*2+1]=0.f; }
        }
    }
    block_stats(acc, (float*)smem, (float*)(smem + 2048), blockIdx.x);
}

// ---------------- small kernels ----------------
__global__ void k_prep_all(const float* __restrict__ Wv, const float* __restrict__ Wo,
                           const float* __restrict__ W1, const float* __restrict__ W2){
    int idx = blockIdx.x*256 + threadIdx.x;
    if (idx < 49152){
        int l = idx / (DCH*DCH);
        int rmd = idx % (DCH*DCH);
        int d = rmd / DCH, col = rmd % DCH;
        int g = col >> 4, k = col & 15;
        float v = Wv[((l*8 + g)*DCH + d)*16 + k];
        __nv_bfloat16 h = __float2bfloat16(v);
        g_wv_hi[idx] = h;
        g_wv_lo[idx] = __float2bfloat16(v - __bfloat162float(h));
    } else if (idx < 98304){
        int i = idx - 49152;
        float v = Wo[i];
        __nv_bfloat16 h = __float2bfloat16(v);
        g_wo_hi[i] = h; g_wo_lo[i] = __float2bfloat16(v - __bfloat162float(h));
    } else if (idx < 294912){
        int i = idx - 98304;
        float v = W1[i];
        __nv_bfloat16 h = __float2bfloat16(v);
        g_w1_hi[i] = h; g_w1_lo[i] = __float2bfloat16(v - __bfloat162float(h));
    } else if (idx < 491520){
        int i = idx - 294912;
        float v = W2[i];
        __nv_bfloat16 h = __float2bfloat16(v);
        g_w2_hi[i] = h; g_w2_lo[i] = __float2bfloat16(v - __bfloat162float(h));
    } else if (idx < 511520){
        g_mask[idx - 491520] = 0;
    }
}

__global__ void k_scatter_mask(const int* __restrict__ ei, int E){
    int e = blockIdx.x*256 + threadIdx.x;
    if (e < E) g_mask[ei[E + e]] = 1;   // dst row
}

// x -> h split (layer 0 input)
__global__ void k_split_x(const float4* __restrict__ x){
    int i = blockIdx.x*256 + threadIdx.x;     // 640000 float4 exactly
    float4 v = x[i];
    unsigned h0,l0,h1,l1;
    split2(v.x, v.y, h0, l0);
    split2(v.z, v.w, h1, l1);
    *(uint2*)(g_h_hi + (size_t)i*4) = make_uint2(h0, h1);
    *(uint2*)(g_h_lo + (size_t)i*4) = make_uint2(l0, l1);
}

__global__ void k_finalize(int nslots, const float* __restrict__ w,
                           const float* __restrict__ b, int which){
    int c = threadIdx.x;   // 128
    float s = 0.f, q = 0.f;
    for (int i = 0; i < nslots; i++){ s += g_part[i*128 + c]; q += g_part2[i*128 + c]; }
    float inv = 1.f / (float)MROWS;
    float mu = s * inv;
    float var = q * inv - mu*mu;
    float sc = rsqrtf(var + 1e-5f) * w[c];
    if (which == 1){ g_scale1[c] = sc; g_shift1[c] = b[c] - mu*sc; }
    else           { g_scale2[c] = sc; g_shift2[c] = b[c] - mu*sc; }
}

// BN1 apply + split: y0 -> z
__global__ void k_bnsplit(){
    int i = blockIdx.x*256 + threadIdx.x;     // 640000 float4
    float4 v = ((const float4*)g_y0)[i];
    int c = (i & 31) << 2;
    v.x = fmaf(v.x, g_scale1[c+0], g_shift1[c+0]);
    v.y = fmaf(v.y, g_scale1[c+1], g_shift1[c+1]);
    v.z = fmaf(v.z, g_scale1[c+2], g_shift1[c+2]);
    v.w = fmaf(v.w, g_scale1[c+3], g_shift1[c+3]);
    unsigned h0,l0,h1,l1;
    split2(v.x, v.y, h0, l0);
    split2(v.z, v.w, h1, l1);
    *(uint2*)(g_z_hi + (size_t)i*4) = make_uint2(h0, h1);
    *(uint2*)(g_z_lo + (size_t)i*4) = make_uint2(l0, l1);
}

// BN2 apply: y1 -> h split (next layer) or fp32 out (last layer)
__global__ void k_bn2(int last, float4* __restrict__ out){
    int i = blockIdx.x*256 + threadIdx.x;
    float4 v = ((const float4*)g_y1)[i];
    int c = (i & 31) << 2;
    v.x = fmaf(v.x, g_scale2[c+0], g_shift2[c+0]);
    v.y = fmaf(v.y, g_scale2[c+1], g_shift2[c+1]);
    v.z = fmaf(v.z, g_scale2[c+2], g_shift2[c+2]);
    v.w = fmaf(v.w, g_scale2[c+3], g_shift2[c+3]);
    if (last){
        out[i] = v;
    } else {
        unsigned h0,l0,h1,l1;
        split2(v.x, v.y, h0, l0);
        split2(v.z, v.w, h1, l1);
        *(uint2*)(g_h_hi + (size_t)i*4) = make_uint2(h0, h1);
        *(uint2*)(g_h_lo + (size_t)i*4) = make_uint2(l0, l1);
    }
}

// ---------------- launch ----------------
extern "C" void kernel_launch(void* const* d_in, const int* in_sizes, int n_in,
                              void* d_out, int out_size) {
    const float* x    = (const float*)d_in[0];
    const int*   ei   = (const int*)  d_in[1];
    const float* Wv   = (const float*)d_in[4];
    const float* Wout = (const float*)d_in[5];
    const float* bn1w = (const float*)d_in[6];
    const float* bn1b = (const float*)d_in[7];
    const float* W1   = (const float*)d_in[8];
    const float* b1   = (const float*)d_in[9];
    const float* W2   = (const float*)d_in[10];
    const float* b2   = (const float*)d_in[11];
    const float* bn2w = (const float*)d_in[12];
    const float* bn2b = (const float*)d_in[13];
    float* out = (float*)d_out;
    int E = in_sizes[1] / 2;

    cudaFuncSetAttribute(k_gemm_v,   cudaFuncAttributeMaxDynamicSharedMemorySize, SMEM_TOT);
    cudaFuncSetAttribute(k_gemm_gat, cudaFuncAttributeMaxDynamicSharedMemorySize, SMEM_TOT);
    cudaFuncSetAttribute(k_gemm_ff1, cudaFuncAttributeMaxDynamicSharedMemorySize, SMEM_TOT);
    cudaFuncSetAttribute(k_gemm_ff2, cudaFuncAttributeMaxDynamicSharedMemorySize, SMEM_TOT);

    k_prep_all<<<1999, 256>>>(Wv, Wout, W1, W2);
    k_scatter_mask<<<(E + 255)/256, 256>>>(ei, E);
    k_split_x<<<2500, 256>>>((const float4*)x);

    for (int l = 0; l < 3; l++){
        k_gemm_v  <<<NBLK, 128, SMEM_TOT>>>(l);
        k_gemm_gat<<<NBLK, 128, SMEM_TOT>>>(l);
        k_finalize<<<1, 128>>>(NBLK, bn1w + l*128, bn1b + l*128, 1);
        k_bnsplit <<<2500, 256>>>();
        dim3 gf(NBLK, 4);
        k_gemm_ff1<<<gf, 128, SMEM_TOT>>>(l, b1 + l*512);
        k_gemm_ff2<<<NBLK, 128, SMEM_TOT>>>(l, b2 + l*128);
        k_finalize<<<1, 128>>>(NBLK, bn2w + l*128, bn2b + l*128, 2);
        k_bn2     <<<2500, 256>>>((l == 2) ? 1 : 0, (float4*)out);
    }
}

// round 17
// speedup vs baseline: 1.0633x; 1.0374x over previous
#include <cuda_runtime.h>
#include <cuda_bf16.h>

#define MROWS 20000
#define DCH   128
#define FFH   512
#define BM    64
#define BN    64
#define BK    32
#define NBLK  313
#define ASTR  40      // halves per A row (32 data + 8 pad) = 80B
#define BSTR  72      // halves per B row (64 data + 8 pad) = 144B

#define A_PLANE 5120                  // 64*80
#define B_PLANE 4608                  // 32*144
#define OFF_BH  (2*A_PLANE)
#define STAGE_B (2*A_PLANE + 2*B_PLANE)   // 19456
#define SMEM_TOT (2*STAGE_B)              // 38912 (<48KB, no opt-in needed)

// ---------------- scratch ----------------
__device__ __nv_bfloat16 g_wv_hi[3*DCH*DCH], g_wv_lo[3*DCH*DCH];
__device__ __nv_bfloat16 g_wo_hi[3*DCH*DCH], g_wo_lo[3*DCH*DCH];
__device__ __nv_bfloat16 g_w1_hi[3*DCH*FFH], g_w1_lo[3*DCH*FFH];
__device__ __nv_bfloat16 g_w2_hi[3*FFH*DCH], g_w2_lo[3*FFH*DCH];
__device__ __nv_bfloat16 g_P_hi[MROWS*DCH],  g_P_lo[MROWS*DCH];   // permuted V
__device__ __nv_bfloat16 g_f_hi[MROWS*FFH],  g_f_lo[MROWS*FFH];   // relu(ff1)
__device__ float g_y0[MROWS*DCH];     // pre-BN1 fp32
__device__ float g_y1[MROWS*DCH];     // pre-BN2 fp32
__device__ float g_part [NBLK*DCH], g_part2[NBLK*DCH];
__device__ float g_scale1[DCH], g_shift1[DCH], g_scale2[DCH], g_shift2[DCH];
__device__ unsigned char g_mask[MROWS];

// ---------------- helpers ----------------
__device__ __forceinline__ unsigned sptr(const void* p){
    return (unsigned)__cvta_generic_to_shared(p);
}
__device__ __forceinline__ void split2(float a, float b, unsigned& hi, unsigned& lo){
    __nv_bfloat16 ha = __float2bfloat16(a), hb = __float2bfloat16(b);
    float ra = a - __bfloat162float(ha);
    float rb = b - __bfloat162float(hb);
    __nv_bfloat162 H; H.x = ha; H.y = hb;
    __nv_bfloat162 L = __floats2bfloat162_rn(ra, rb);
    hi = *reinterpret_cast<unsigned*>(&H);
    lo = *reinterpret_cast<unsigned*>(&L);
}
__device__ __forceinline__ void ldsm4(unsigned r[4], unsigned a){
    asm volatile("ldmatrix.sync.aligned.m8n8.x4.shared.b16 {%0,%1,%2,%3}, [%4];"
        : "=r"(r[0]), "=r"(r[1]), "=r"(r[2]), "=r"(r[3]) : "r"(a));
}
__device__ __forceinline__ void ldsm4t(unsigned r[4], unsigned a){
    asm volatile("ldmatrix.sync.aligned.m8n8.x4.trans.shared.b16 {%0,%1,%2,%3}, [%4];"
        : "=r"(r[0]), "=r"(r[1]), "=r"(r[2]), "=r"(r[3]) : "r"(a));
}
__device__ __forceinline__ void mma_b(float c[4], const unsigned a[4], unsigned b0, unsigned b1){
    asm volatile("mma.sync.aligned.m16n8k16.row.col.f32.bf16.bf16.f32 "
        "{%0,%1,%2,%3}, {%4,%5,%6,%7}, {%8,%9}, {%0,%1,%2,%3};"
        : "+f"(c[0]), "+f"(c[1]), "+f"(c[2]), "+f"(c[3])
        : "r"(a[0]), "r"(a[1]), "r"(a[2]), "r"(a[3]), "r"(b0), "r"(b1));
}
__device__ __forceinline__ void cpa(unsigned d, const void* s, int sz){
    asm volatile("cp.async.cg.shared.global [%0], [%1], 16, %2;"
        :: "r"(d), "l"(s), "r"(sz));
}
__device__ __forceinline__ void cpa16(unsigned d, const void* s){
    asm volatile("cp.async.cg.shared.global [%0], [%1], 16;" :: "r"(d), "l"(s));
}

// ---------------- compute: one 64x64x32 stage, 3-pass split ----------------
// 4 warps: 2m x 2n, warp tile 32x32
__device__ __forceinline__ void compute_stage(unsigned base, float acc[2][4][4]){
    int lane = threadIdx.x & 31;
    int warp = threadIdx.x >> 5;
    int wm = warp >> 1, wn = warp & 1;
    unsigned saH = base, saL = base + A_PLANE;
    unsigned sbH = base + OFF_BH, sbL = base + OFF_BH + B_PLANE;
    #pragma unroll
    for (int ks = 0; ks < 2; ks++){
        unsigned aH[2][4], aL[2][4];
        #pragma unroll
        for (int mt = 0; mt < 2; mt++){
            unsigned aoff = (unsigned)((wm*32 + mt*16 + (lane & 15))*(ASTR*2)
                                       + ks*32 + ((lane >> 4) << 4));
            ldsm4(aH[mt], saH + aoff);
            ldsm4(aL[mt], saL + aoff);
        }
        #pragma unroll
        for (int p = 0; p < 2; p++){
            int kk = ks*16 + (lane & 15);
            int n  = wn*32 + p*16 + ((lane & 16) ? 8 : 0);
            unsigned boff = (unsigned)(kk*(BSTR*2) + n*2);
            unsigned t[4], u[4];
            ldsm4t(t, sbH + boff);
            ldsm4t(u, sbL + boff);
            #pragma unroll
            for (int mt = 0; mt < 2; mt++){
                mma_b(acc[mt][2*p],   aH[mt], t[0], t[1]);
                mma_b(acc[mt][2*p+1], aH[mt], t[2], t[3]);
                mma_b(acc[mt][2*p],   aL[mt], t[0], t[1]);
                mma_b(acc[mt][2*p+1], aL[mt], t[2], t[3]);
                mma_b(acc[mt][2*p],   aH[mt], u[0], u[1]);
                mma_b(acc[mt][2*p+1], aH[mt], u[2], u[3]);
            }
        }
    }
}

// ---------------- pipelined mainloop (double-buffered, 128 threads) ----------------
// AF32: A loaded as fp32 (+optional BN scale), split to bf16 in the loader.
template<int S, bool AF32>
__device__ __forceinline__ void gemm_main(char* smem,
    const float* __restrict__ Af, const float* __restrict__ scl, const float* __restrict__ sft,
    const __nv_bfloat16* __restrict__ Ah, const __nv_bfloat16* __restrict__ Al, int lda,
    int row0,
    const __nv_bfloat16* __restrict__ Bh, const __nv_bfloat16* __restrict__ Bl, int ldb, int col0,
    float acc[2][4][4])
{
    unsigned base0 = sptr(smem);
    int tid = threadIdx.x;

    auto loadStage = [&](int s){
        int k0 = s*BK;
        unsigned b = base0 + (unsigned)((s & 1)*STAGE_B);
        char* bp = smem + (s & 1)*STAGE_B;
        if (AF32){
            #pragma unroll
            for (int i = 0; i < 2; i++){
                int j = tid + i*128;
                int r = j >> 2, c8 = (j & 3) << 3;   // 8 floats per chunk
                int gr = row0 + r;
                float v[8];
                if (gr < MROWS){
                    float4 p0 = *(const float4*)(Af + (size_t)gr*DCH + k0 + c8);
                    float4 p1 = *(const float4*)(Af + (size_t)gr*DCH + k0 + c8 + 4);
                    v[0]=p0.x; v[1]=p0.y; v[2]=p0.z; v[3]=p0.w;
                    v[4]=p1.x; v[5]=p1.y; v[6]=p1.z; v[7]=p1.w;
                    if (scl){
                        #pragma unroll
                        for (int e = 0; e < 8; e++)
                            v[e] = fmaf(v[e], scl[k0+c8+e], sft[k0+c8+e]);
                    }
                } else {
                    #pragma unroll
                    for (int e = 0; e < 8; e++) v[e] = 0.f;
                }
                unsigned hi[4], lo[4];
                #pragma unroll
                for (int e = 0; e < 4; e++) split2(v[2*e], v[2*e+1], hi[e], lo[e]);
                *(uint4*)(bp + r*(ASTR*2) + c8*2)           = make_uint4(hi[0],hi[1],hi[2],hi[3]);
                *(uint4*)(bp + A_PLANE + r*(ASTR*2) + c8*2) = make_uint4(lo[0],lo[1],lo[2],lo[3]);
            }
        } else {
            #pragma unroll
            for (int i = 0; i < 2; i++){
                int j = tid + i*128;
                int r = j >> 2, c8 = (j & 3) << 3;   // 8 halves per chunk
                int gr = row0 + r;
                int sz = (gr < MROWS) ? 16 : 0;
                int grc = (gr < MROWS) ? gr : (MROWS - 1);
                size_t go = (size_t)grc*lda + k0 + c8;
                cpa(b + (unsigned)(r*(ASTR*2) + c8*2),           Ah + go, sz);
                cpa(b + A_PLANE + (unsigned)(r*(ASTR*2) + c8*2), Al + go, sz);
            }
        }
        #pragma unroll
        for (int i = 0; i < 2; i++){
            int j = tid + i*128;
            int r = j >> 3, c8 = (j & 7) << 3;       // 32 rows x 64 halves
            size_t go = (size_t)(k0 + r)*ldb + col0 + c8;
            cpa16(b + OFF_BH + (unsigned)(r*(BSTR*2) + c8*2),           Bh + go);
            cpa16(b + OFF_BH + B_PLANE + (unsigned)(r*(BSTR*2) + c8*2), Bl + go);
        }
        asm volatile("cp.async.commit_group;" ::: "memory");
    };

    loadStage(0);
    for (int s = 0; s < S; s++){
        if (s + 1 < S){
            loadStage(s + 1);
            asm volatile("cp.async.wait_group 1;" ::: "memory");
        } else {
            asm volatile("cp.async.wait_group 0;" ::: "memory");
        }
        __syncthreads();
        compute_stage(base0 + (unsigned)((s & 1)*STAGE_B), acc);
        __syncthreads();
    }
}

// deterministic per-block (64-col half) column sums from epilogue values in acc
__device__ __forceinline__ void stats64(float acc[2][4][4], char* smem, int slot, int colhalf)
{
    int tid = threadIdx.x;
    int lane = tid & 31, warp = tid >> 5, wm = warp >> 1, wn = warp & 1;
    float* redS = (float*)smem;           // 128 floats
    float* redQ = (float*)(smem + 512);   // 128 floats
    #pragma unroll
    for (int nt = 0; nt < 4; nt++){
        float s0=0.f, s1=0.f, q0=0.f, q1=0.f;
        #pragma unroll
        for (int mt = 0; mt < 2; mt++){
            float a0=acc[mt][nt][0], a1=acc[mt][nt][1], a2=acc[mt][nt][2], a3=acc[mt][nt][3];
            s0 += a0 + a2; s1 += a1 + a3;
            q0 += a0*a0 + a2*a2; q1 += a1*a1 + a3*a3;
        }
        #pragma unroll
        for (int off = 16; off >= 4; off >>= 1){
            s0 += __shfl_down_sync(0xffffffffu, s0, off);
            s1 += __shfl_down_sync(0xffffffffu, s1, off);
            q0 += __shfl_down_sync(0xffffffffu, q0, off);
            q1 += __shfl_down_sync(0xffffffffu, q1, off);
        }
        if (lane < 4){
            int c = wn*32 + nt*8 + lane*2;
            redS[wm*64 + c] = s0; redS[wm*64 + c + 1] = s1;
            redQ[wm*64 + c] = q0; redQ[wm*64 + c + 1] = q1;
        }
    }
    __syncthreads();
    if (tid < 64){
        g_part [slot*128 + colhalf*64 + tid] = redS[tid] + redS[64 + tid];
        g_part2[slot*128 + colhalf*64 + tid] = redQ[tid] + redQ[64 + tid];
    }
}

#define ACC_INIT float acc[2][4][4]; \
    _Pragma("unroll") for (int _i=0;_i<2;_i++) \
    _Pragma("unroll") for (int _j=0;_j<4;_j++) \
    _Pragma("unroll") for (int _k=0;_k<4;_k++) acc[_i][_j][_k]=0.f;

#define EPI_COORDS int tid = threadIdx.x; int lane = tid & 31; int warp = tid >> 5; \
    int wm = warp >> 1, wn = warp & 1; \
    int rb = row0 + wm*32 + (lane>>2); \
    int gc = col0 + wn*32 + ((lane&3)<<1); (void)tid;

// ---------------- GEMM 1: P(permuted,split) = BN2h @ Wv ----------------
__global__ __launch_bounds__(128, 4) void k_gemm_v(int l, const float* __restrict__ xsrc)
{
    extern __shared__ char smem[];
    ACC_INIT
    int row0 = blockIdx.x*BM, col0 = blockIdx.y*BN;
    const float* Af  = xsrc ? xsrc : g_y1;
    const float* scl = xsrc ? (const float*)nullptr : g_scale2;
    const float* sft = xsrc ? (const float*)nullptr : g_shift2;
    gemm_main<4, true>(smem, Af, scl, sft, nullptr, nullptr, 0, row0,
                       g_wv_hi + l*DCH*DCH, g_wv_lo + l*DCH*DCH, DCH, col0, acc);
    EPI_COORDS
    #pragma unroll
    for (int mt = 0; mt < 2; mt++)
    #pragma unroll
    for (int hf = 0; hf < 2; hf++){
        int r = rb + mt*16 + hf*8;
        if (r < MROWS){
            int m = r >> 3, rr = r & 7;
            #pragma unroll
            for (int nt = 0; nt < 4; nt++){
                int c = gc + nt*8;
                int g = c >> 4;
                size_t off = (size_t)(g*2500 + m)*DCH + (rr << 4) + (c & 15);
                unsigned hi, lo;
                split2(acc[mt][nt][hf*2], acc[mt][nt][hf*2+1], hi, lo);
                *(unsigned*)(g_P_hi + off) = hi;
                *(unsigned*)(g_P_lo + off) = lo;
            }
        }
    }
}

// ---------------- GEMM 2: y0 = resid + mask*(P @ Wout); BN1 partial stats ----------------
__global__ __launch_bounds__(128, 4) void k_gemm_gat(int l, const float* __restrict__ xres)
{
    extern __shared__ char smem[];
    ACC_INIT
    int row0 = blockIdx.x*BM, col0 = blockIdx.y*BN;
    gemm_main<4, false>(smem, nullptr, nullptr, nullptr, g_P_hi, g_P_lo, DCH, row0,
                        g_wo_hi + l*DCH*DCH, g_wo_lo + l*DCH*DCH, DCH, col0, acc);
    EPI_COORDS
    #pragma unroll
    for (int mt = 0; mt < 2; mt++)
    #pragma unroll
    for (int hf = 0; hf < 2; hf++){
        int r = rb + mt*16 + hf*8;
        if (r < MROWS){
            float mk = g_mask[r] ? 1.f : 0.f;
            #pragma unroll
            for (int nt = 0; nt < 4; nt++){
                int c = gc + nt*8;
                float h0, h1;
                if (xres){
                    float2 xv = *(const float2*)(xres + (size_t)r*DCH + c);
                    h0 = xv.x; h1 = xv.y;
                } else {
                    float2 yv = *(const float2*)(g_y1 + (size_t)r*DCH + c);
                    h0 = fmaf(yv.x, g_scale2[c],   g_shift2[c]);
                    h1 = fmaf(yv.y, g_scale2[c+1], g_shift2[c+1]);
                }
                float v0 = fmaf(mk, acc[mt][nt][hf*2+0], h0);
                float v1 = fmaf(mk, acc[mt][nt][hf*2+1], h1);
                *(float2*)(g_y0 + (size_t)r*DCH + c) = make_float2(v0, v1);
                acc[mt][nt][hf*2+0] = v0; acc[mt][nt][hf*2+1] = v1;
            }
        } else {
            #pragma unroll
            for (int nt = 0; nt < 4; nt++){ acc[mt][nt][hf*2+0]=0.f; acc[mt][nt][hf*2+1]=0.f; }
        }
    }
    stats64(acc, smem, blockIdx.x, blockIdx.y);
}

// ---------------- GEMM 3: f = relu(BN1(y0) @ W1 + b1), split output ----------------
__global__ __launch_bounds__(128, 4) void k_gemm_ff1(int l, const float* __restrict__ bias)
{
    extern __shared__ char smem[];
    ACC_INIT
    int row0 = blockIdx.x*BM, col0 = blockIdx.y*BN;
    gemm_main<4, true>(smem, g_y0, g_scale1, g_shift1, nullptr, nullptr, 0, row0,
                       g_w1_hi + l*DCH*FFH, g_w1_lo + l*DCH*FFH, FFH, col0, acc);
    EPI_COORDS
    #pragma unroll
    for (int mt = 0; mt < 2; mt++)
    #pragma unroll
    for (int hf = 0; hf < 2; hf++){
        int r = rb + mt*16 + hf*8;
        if (r < MROWS){
            #pragma unroll
            for (int nt = 0; nt < 4; nt++){
                int c = gc + nt*8;
                float v0 = fmaxf(acc[mt][nt][hf*2+0] + bias[c],   0.f);
                float v1 = fmaxf(acc[mt][nt][hf*2+1] + bias[c+1], 0.f);
                unsigned hi, lo;
                split2(v0, v1, hi, lo);
                size_t off = (size_t)r*FFH + c;
                *(unsigned*)(g_f_hi + off) = hi;
                *(unsigned*)(g_f_lo + off) = lo;
            }
        }
    }
}

// ---------------- GEMM 4: y1 = BN1(y0) + f @ W2 + b2; BN2 partial stats ----------------
__global__ __launch_bounds__(128, 4) void k_gemm_ff2(int l, const float* __restrict__ bias)
{
    extern __shared__ char smem[];
    ACC_INIT
    int row0 = blockIdx.x*BM, col0 = blockIdx.y*BN;
    gemm_main<16, false>(smem, nullptr, nullptr, nullptr, g_f_hi, g_f_lo, FFH, row0,
                         g_w2_hi + l*FFH*DCH, g_w2_lo + l*FFH*DCH, DCH, col0, acc);
    EPI_COORDS
    #pragma unroll
    for (int mt = 0; mt < 2; mt++)
    #pragma unroll
    for (int hf = 0; hf < 2; hf++){
        int r = rb + mt*16 + hf*8;
        if (r < MROWS){
            #pragma unroll
            for (int nt = 0; nt < 4; nt++){
                int c = gc + nt*8;
                float2 yv = *(const float2*)(g_y0 + (size_t)r*DCH + c);
                float z0 = fmaf(yv.x, g_scale1[c],   g_shift1[c]);
                float z1 = fmaf(yv.y, g_scale1[c+1], g_shift1[c+1]);
                float v0 = z0 + acc[mt][nt][hf*2+0] + bias[c];
                float v1 = z1 + acc[mt][nt][hf*2+1] + bias[c+1];
                *(float2*)(g_y1 + (size_t)r*DCH + c) = make_float2(v0, v1);
                acc[mt][nt][hf*2+0] = v0; acc[mt][nt][hf*2+1] = v1;
            }
        } else {
            #pragma unroll
            for (int nt = 0; nt < 4; nt++){ acc[mt][nt][hf*2+0]=0.f; acc[mt][nt][hf*2+1]=0.f; }
        }
    }
    stats64(acc, smem, blockIdx.x, blockIdx.y);
}

// ---------------- small kernels ----------------
__global__ void k_prep_all(const float* __restrict__ Wv, const float* __restrict__ Wo,
                           const float* __restrict__ W1, const float* __restrict__ W2){
    int idx = blockIdx.x*256 + threadIdx.x;
    if (idx < 49152){
        int l = idx / (DCH*DCH);
        int rmd = idx % (DCH*DCH);
        int d = rmd / DCH, col = rmd % DCH;
        int g = col >> 4, k = col & 15;
        float v = Wv[((l*8 + g)*DCH + d)*16 + k];
        __nv_bfloat16 h = __float2bfloat16(v);
        g_wv_hi[idx] = h;
        g_wv_lo[idx] = __float2bfloat16(v - __bfloat162float(h));
    } else if (idx < 98304){
        int i = idx - 49152;
        float v = Wo[i];
        __nv_bfloat16 h = __float2bfloat16(v);
        g_wo_hi[i] = h; g_wo_lo[i] = __float2bfloat16(v - __bfloat162float(h));
    } else if (idx < 294912){
        int i = idx - 98304;
        float v = W1[i];
        __nv_bfloat16 h = __float2bfloat16(v);
        g_w1_hi[i] = h; g_w1_lo[i] = __float2bfloat16(v - __bfloat162float(h));
    } else if (idx < 491520){
        int i = idx - 294912;
        float v = W2[i];
        __nv_bfloat16 h = __float2bfloat16(v);
        g_w2_hi[i] = h; g_w2_lo[i] = __float2bfloat16(v - __bfloat162float(h));
    } else if (idx < 511520){
        g_mask[idx - 491520] = 0;
    }
}

__global__ void k_scatter_mask(const int* __restrict__ ei, int E){
    int e = blockIdx.x*256 + threadIdx.x;
    if (e < E) g_mask[ei[E + e]] = 1;   // dst row
}

__global__ void k_finalize(const float* __restrict__ w, const float* __restrict__ b, int which){
    int c = threadIdx.x;   // 128
    float s = 0.f, q = 0.f;
    for (int i = 0; i < NBLK; i++){ s += g_part[i*128 + c]; q += g_part2[i*128 + c]; }
    float inv = 1.f / (float)MROWS;
    float mu = s * inv;
    float var = q * inv - mu*mu;
    float sc = rsqrtf(var + 1e-5f) * w[c];
    if (which == 1){ g_scale1[c] = sc; g_shift1[c] = b[c] - mu*sc; }
    else           { g_scale2[c] = sc; g_shift2[c] = b[c] - mu*sc; }
}

// final BN2 apply: y1 -> out
__global__ void k_out(float4* __restrict__ out){
    int i = blockIdx.x*256 + threadIdx.x;   // 640000 float4 exactly
    float4 v = ((const float4*)g_y1)[i];
    int c = (i & 31) << 2;
    v.x = fmaf(v.x, g_scale2[c+0], g_shift2[c+0]);
    v.y = fmaf(v.y, g_scale2[c+1], g_shift2[c+1]);
    v.z = fmaf(v.z, g_scale2[c+2], g_shift2[c+2]);
    v.w = fmaf(v.w, g_scale2[c+3], g_shift2[c+3]);
    out[i] = v;
}

// ---------------- launch ----------------
extern "C" void kernel_launch(void* const* d_in, const int* in_sizes, int n_in,
                              void* d_out, int out_size) {
    const float* x    = (const float*)d_in[0];
    const int*   ei   = (const int*)  d_in[1];
    const float* Wv   = (const float*)d_in[4];
    const float* Wout = (const float*)d_in[5];
    const float* bn1w = (const float*)d_in[6];
    const float* bn1b = (const float*)d_in[7];
    const float* W1   = (const float*)d_in[8];
    const float* b1   = (const float*)d_in[9];
    const float* W2   = (const float*)d_in[10];
    const float* b2   = (const float*)d_in[11];
    const float* bn2w = (const float*)d_in[12];
    const float* bn2b = (const float*)d_in[13];
    float* out = (float*)d_out;
    int E = in_sizes[1] / 2;

    k_prep_all<<<1999, 256>>>(Wv, Wout, W1, W2);
    k_scatter_mask<<<(E + 255)/256, 256>>>(ei, E);

    for (int l = 0; l < 3; l++){
        const float* ext = (l == 0) ? x : nullptr;
        k_gemm_v  <<<dim3(NBLK, 2), 128, SMEM_TOT>>>(l, ext);
        k_gemm_gat<<<dim3(NBLK, 2), 128, SMEM_TOT>>>(l, ext);
        k_finalize<<<1, 128>>>(bn1w + l*128, bn1b + l*128, 1);
        k_gemm_ff1<<<dim3(NBLK, 8), 128, SMEM_TOT>>>(l, b1 + l*512);
        k_gemm_ff2<<<dim3(NBLK, 2), 128, SMEM_TOT>>>(l, b2 + l*128);
        k_finalize<<<1, 128>>>(bn2w + l*128, bn2b + l*128, 2);
    }
    k_out<<<2500, 256>>>((float4*)out);
}